// round 5
// baseline (speedup 1.0000x reference)
#include <cuda_runtime.h>
#include <math_constants.h>

// ChamferLoss via exact grid-accelerated NN, cell-sorted queries, and a
// fully-unrolled 3x3x3 neighborhood scan (18 independent range loads, MLP=18).
// d2min(p -> Q) = |p|^2 - 2 * max_j ( p.q_j - 0.5|q_j|^2 )
//
// 16 structures, one per (cloud, batch):
//   s in [0,8):  nonfiltered (0-3: pn, 4-7: gn), 8192 pts
//   s in [8,16): filtered    (8-11: pf, 12-15: gf), 4096 pts
// Structure s's points query partner structure s^4.
//
// Exactness: after completing all Chebyshev rings <= r, any unscanned point is
// >= r*H away (clamping = per-axis 1-Lipschitz projection), so stopping when
// best_d2 <= ((r-1)*H)^2 is exact. Row clamping in the 3x3x3 cube may rescan
// a boundary row twice; max is idempotent so this is harmless.

#define G     32
#define NCELL (G * G * G)
#define H     0.32f
#define INVH  3.125f
#define RANGE 5.12f
#define NSTRUCT 16
#define CAP   8192

#define NQ_TOTAL 98304

__device__ int    g_cnt  [NSTRUCT * NCELL];
__device__ int    g_start[NSTRUCT * NCELL];
__device__ int    g_cur  [NSTRUCT * NCELL];
__device__ float4 g_pts  [NSTRUCT * CAP];   // cell-sorted (x,y,z,-0.5|q|^2)

__device__ __forceinline__ int cell_coord(float x) {
    int c = (int)floorf((x + RANGE) * INVH);
    return min(max(c, 0), G - 1);
}

__device__ __forceinline__ const float* map_point(
    int t, const float* pf, const float* gf, const float* pn, const float* gn,
    int* idx, int* s)
{
    if (t < 65536) {
        const int grp = t >> 13;
        *idx = t & 8191;
        *s   = grp;
        return ((grp < 4) ? pn : gn) + (size_t)(grp & 3) * 8192 * 3;
    } else {
        const int tf  = t - 65536;
        const int grp = tf >> 12;
        *idx = tf & 4095;
        *s   = 8 + grp;
        return ((grp < 4) ? pf : gf) + (size_t)(grp & 3) * 4096 * 3;
    }
}

__global__ void k_zero(float* out) {
    const int i = blockIdx.x * 1024 + threadIdx.x;
    if (i < NSTRUCT * NCELL) g_cnt[i] = 0;
    if (i == 0) out[0] = 0.0f;
}

__global__ __launch_bounds__(256) void k_count(
    const float* __restrict__ pf, const float* __restrict__ gf,
    const float* __restrict__ pn, const float* __restrict__ gn)
{
    const int t = blockIdx.x * 256 + threadIdx.x;
    int i, s;
    const float* P = map_point(t, pf, gf, pn, gn, &i, &s);
    const float x = P[3 * i], y = P[3 * i + 1], z = P[3 * i + 2];
    const int cell = (cell_coord(z) * G + cell_coord(y)) * G + cell_coord(x);
    atomicAdd(&g_cnt[s * NCELL + cell], 1);
}

__global__ __launch_bounds__(1024) void k_scan() {
    const int s   = blockIdx.x;
    const int tid = threadIdx.x;
    const int CPT = NCELL / 1024;
    const int base = s * NCELL + tid * CPT;

    int sum = 0;
    #pragma unroll
    for (int k = 0; k < CPT; k++) sum += g_cnt[base + k];

    __shared__ int sh[1024];
    sh[tid] = sum;
    __syncthreads();
    #pragma unroll
    for (int off = 1; off < 1024; off <<= 1) {
        int v = (tid >= off) ? sh[tid - off] : 0;
        __syncthreads();
        sh[tid] += v;
        __syncthreads();
    }
    int run = (tid == 0) ? 0 : sh[tid - 1];

    #pragma unroll
    for (int k = 0; k < CPT; k++) {
        const int c = g_cnt[base + k];
        g_start[base + k] = run;
        g_cur[base + k]   = run;
        run += c;
    }
}

__global__ __launch_bounds__(256) void k_scatter(
    const float* __restrict__ pf, const float* __restrict__ gf,
    const float* __restrict__ pn, const float* __restrict__ gn)
{
    const int t = blockIdx.x * 256 + threadIdx.x;
    int i, s;
    const float* P = map_point(t, pf, gf, pn, gn, &i, &s);
    const float x = P[3 * i], y = P[3 * i + 1], z = P[3 * i + 2];
    const int cell = (cell_coord(z) * G + cell_coord(y)) * G + cell_coord(x);
    const int slot = atomicAdd(&g_cur[s * NCELL + cell], 1);
    const float nh = -0.5f * fmaf(x, x, fmaf(y, y, z * z));
    g_pts[s * CAP + slot] = make_float4(x, y, z, nh);
}

#define QBLK 128

__global__ __launch_bounds__(QBLK) void k_query(float* __restrict__ out)
{
    const int t = blockIdx.x * QBLK + threadIdx.x;
    int s_own, u;
    float scale;
    if (t < 65536) {
        s_own = t >> 13;
        u     = t & 8191;
        scale = 0.3f / (4.0f * 8192.0f);
    } else {
        const int tf = t - 65536;
        s_own = 8 + (tf >> 12);
        u     = tf & 4095;
        scale = 0.7f / (4.0f * 4096.0f);
    }
    const int s = s_own ^ 4;

    const float4 p  = g_pts[s_own * CAP + u];
    const float px = p.x, py = p.y, pz = p.z;
    const float p2 = -2.0f * p.w;
    const int cx = cell_coord(px), cy = cell_coord(py), cz = cell_coord(pz);

    const int*    st  = g_start + s * NCELL;
    const int*    cu  = g_cur   + s * NCELL;
    const float4* pts = g_pts   + s * CAP;

    float m = -CUDART_INF_F;

    // ---- rings 0..1: fixed 3x3 rows (clamped; dup rows OK: max idempotent) ----
    {
        const int x0 = max(cx - 1, 0), x1 = min(cx + 1, G - 1);
        const int zs0 = max(cz - 1, 0) * G, zs1 = cz * G, zs2 = min(cz + 1, G - 1) * G;
        const int ys0 = max(cy - 1, 0),     ys1 = cy,     ys2 = min(cy + 1, G - 1);

        int rb[9];
        rb[0] = (zs0 + ys0) * G; rb[1] = (zs0 + ys1) * G; rb[2] = (zs0 + ys2) * G;
        rb[3] = (zs1 + ys0) * G; rb[4] = (zs1 + ys1) * G; rb[5] = (zs1 + ys2) * G;
        rb[6] = (zs2 + ys0) * G; rb[7] = (zs2 + ys1) * G; rb[8] = (zs2 + ys2) * G;

        int beg[9], end[9];
        #pragma unroll
        for (int k = 0; k < 9; k++) beg[k] = st[rb[k] + x0];
        #pragma unroll
        for (int k = 0; k < 9; k++) end[k] = cu[rb[k] + x1];

        #pragma unroll
        for (int k = 0; k < 9; k++) {
            for (int v = beg[k]; v < end[k]; v++) {
                const float4 q = pts[v];
                m = fmaxf(m, fmaf(px, q.x, fmaf(py, q.y, fmaf(pz, q.z, q.w))));
            }
        }
    }
    float bd2 = fmaf(-2.0f, m, p2);

    // ---- shells r >= 2 until provably exact (rare path) ----
    for (int r = 2; r < G; r++) {
        const float bound = (float)(r - 1) * H;
        if (bd2 <= bound * bound) break;
        for (int dz = -r; dz <= r; dz++) {
            const int zz = cz + dz;
            if (zz < 0 || zz >= G) continue;
            const bool zf = (dz == -r) || (dz == r);
            for (int dy = -r; dy <= r; dy++) {
                const int yy = cy + dy;
                if (yy < 0 || yy >= G) continue;
                const int rb = (zz * G + yy) * G;
                if (zf || dy == -r || dy == r) {
                    const int x0 = max(cx - r, 0), x1 = min(cx + r, G - 1);
                    const int beg = st[rb + x0], end = cu[rb + x1];
                    for (int v = beg; v < end; v++) {
                        const float4 q = pts[v];
                        m = fmaxf(m, fmaf(px, q.x, fmaf(py, q.y, fmaf(pz, q.z, q.w))));
                    }
                } else {
                    const int xl = cx - r;
                    if (xl >= 0) {
                        const int beg = st[rb + xl], end = cu[rb + xl];
                        for (int v = beg; v < end; v++) {
                            const float4 q = pts[v];
                            m = fmaxf(m, fmaf(px, q.x, fmaf(py, q.y, fmaf(pz, q.z, q.w))));
                        }
                    }
                    const int xr = cx + r;
                    if (xr < G) {
                        const int beg = st[rb + xr], end = cu[rb + xr];
                        for (int v = beg; v < end; v++) {
                            const float4 q = pts[v];
                            m = fmaxf(m, fmaf(px, q.x, fmaf(py, q.y, fmaf(pz, q.z, q.w))));
                        }
                    }
                }
            }
        }
        bd2 = fmaf(-2.0f, m, p2);
    }

    float val = bd2 * scale;

    #pragma unroll
    for (int o = 16; o; o >>= 1)
        val += __shfl_down_sync(0xffffffffu, val, o);
    __shared__ float ws[QBLK / 32];
    if ((threadIdx.x & 31) == 0) ws[threadIdx.x >> 5] = val;
    __syncthreads();
    if (threadIdx.x == 0) {
        float acc = 0.0f;
        #pragma unroll
        for (int w = 0; w < QBLK / 32; w++) acc += ws[w];
        atomicAdd(out, acc);
    }
}

extern "C" void kernel_launch(void* const* d_in, const int* in_sizes, int n_in,
                              void* d_out, int out_size) {
    const float* pf = (const float*)d_in[0];
    const float* gf = (const float*)d_in[1];
    const float* pn = (const float*)d_in[2];
    const float* gn = (const float*)d_in[3];
    float* out = (float*)d_out;

    k_zero<<<(NSTRUCT * NCELL + 1023) / 1024, 1024>>>(out);
    k_count<<<NQ_TOTAL / 256, 256>>>(pf, gf, pn, gn);
    k_scan<<<NSTRUCT, 1024>>>();
    k_scatter<<<NQ_TOTAL / 256, 256>>>(pf, gf, pn, gn);
    k_query<<<NQ_TOTAL / QBLK, QBLK>>>(out);
}

// round 6
// speedup vs baseline: 1.2056x; 1.2056x over previous
#include <cuda_runtime.h>
#include <math_constants.h>

// ChamferLoss via exact grid NN. One WARP per query: parallel row-range
// fetch, lane-strided candidate scan, lane-parallel shell expansion.
// d2min(p -> Q) = |p|^2 - 2 * max_j ( p.q_j - 0.5|q_j|^2 )
//
// 16 structures: s in [0,8) nonfiltered (0-3 pn, 4-7 gn, 8192 pts),
//                s in [8,16) filtered (8-11 pf, 12-15 gf, 4096 pts).
// Structure s queries partner s^4.
//
// Exactness: before scanning shell r, all cells of Chebyshev <= r-1 are done;
// unscanned cells have Chebyshev >= r => point distance >= (r-1)*H (clamping
// is a per-axis 1-Lipschitz projection). Stop when bd2 <= ((r-1)*H)^2.
// Clamped duplicate rows rescan cells; max is idempotent so it's harmless.

#define G     32
#define NCELL (G * G * G)
#define H     0.32f
#define INVH  3.125f
#define RANGE 5.12f
#define NSTRUCT 16
#define CAP   8192

#define NQ_TOTAL 98304
#define QBLOCKS (NQ_TOTAL / 32)   // 3072 blocks, 32 warps each = 1 query/warp

__device__ int    g_cnt  [NSTRUCT * NCELL];
__device__ int    g_start[NSTRUCT * NCELL];
__device__ int    g_cur  [NSTRUCT * NCELL];
__device__ float4 g_pts  [NSTRUCT * CAP];     // cell-sorted (x,y,z,-0.5|q|^2)
__device__ float  g_blocksum[QBLOCKS];

__device__ __forceinline__ int cell_coord(float x) {
    int c = (int)floorf((x + RANGE) * INVH);
    return min(max(c, 0), G - 1);
}

__device__ __forceinline__ const float* map_point(
    int t, const float* pf, const float* gf, const float* pn, const float* gn,
    int* idx, int* s)
{
    if (t < 65536) {
        const int grp = t >> 13;
        *idx = t & 8191;
        *s   = grp;
        return ((grp < 4) ? pn : gn) + (size_t)(grp & 3) * 8192 * 3;
    } else {
        const int tf  = t - 65536;
        const int grp = tf >> 12;
        *idx = tf & 4095;
        *s   = 8 + grp;
        return ((grp < 4) ? pf : gf) + (size_t)(grp & 3) * 4096 * 3;
    }
}

__global__ void k_zero() {
    const int i = blockIdx.x * 1024 + threadIdx.x;
    if (i < NSTRUCT * NCELL) g_cnt[i] = 0;
}

__global__ __launch_bounds__(256) void k_count(
    const float* __restrict__ pf, const float* __restrict__ gf,
    const float* __restrict__ pn, const float* __restrict__ gn)
{
    const int t = blockIdx.x * 256 + threadIdx.x;
    int i, s;
    const float* P = map_point(t, pf, gf, pn, gn, &i, &s);
    const float x = P[3 * i], y = P[3 * i + 1], z = P[3 * i + 2];
    const int cell = (cell_coord(z) * G + cell_coord(y)) * G + cell_coord(x);
    atomicAdd(&g_cnt[s * NCELL + cell], 1);
}

__global__ __launch_bounds__(1024) void k_scan() {
    const int s   = blockIdx.x;
    const int tid = threadIdx.x;
    const int CPT = NCELL / 1024;
    const int base = s * NCELL + tid * CPT;

    int sum = 0;
    #pragma unroll
    for (int k = 0; k < CPT; k++) sum += g_cnt[base + k];

    __shared__ int sh[1024];
    sh[tid] = sum;
    __syncthreads();
    #pragma unroll
    for (int off = 1; off < 1024; off <<= 1) {
        int v = (tid >= off) ? sh[tid - off] : 0;
        __syncthreads();
        sh[tid] += v;
        __syncthreads();
    }
    int run = (tid == 0) ? 0 : sh[tid - 1];

    #pragma unroll
    for (int k = 0; k < CPT; k++) {
        const int c = g_cnt[base + k];
        g_start[base + k] = run;
        g_cur[base + k]   = run;
        run += c;
    }
}

__global__ __launch_bounds__(256) void k_scatter(
    const float* __restrict__ pf, const float* __restrict__ gf,
    const float* __restrict__ pn, const float* __restrict__ gn)
{
    const int t = blockIdx.x * 256 + threadIdx.x;
    int i, s;
    const float* P = map_point(t, pf, gf, pn, gn, &i, &s);
    const float x = P[3 * i], y = P[3 * i + 1], z = P[3 * i + 2];
    const int cell = (cell_coord(z) * G + cell_coord(y)) * G + cell_coord(x);
    const int slot = atomicAdd(&g_cur[s * NCELL + cell], 1);
    const float nh = -0.5f * fmaf(x, x, fmaf(y, y, z * z));
    g_pts[s * CAP + slot] = make_float4(x, y, z, nh);
}

// ---- one warp per query ----
__global__ __launch_bounds__(1024) void k_query()
{
    const int wq   = blockIdx.x * 32 + (threadIdx.x >> 5);  // global query id
    const int lane = threadIdx.x & 31;

    int s_own, u;
    float scale;
    if (wq < 65536) {
        s_own = wq >> 13;
        u     = wq & 8191;
        scale = 0.3f / (4.0f * 8192.0f);
    } else {
        const int tf = wq - 65536;
        s_own = 8 + (tf >> 12);
        u     = tf & 4095;
        scale = 0.7f / (4.0f * 4096.0f);
    }
    const int s = s_own ^ 4;

    const float4 p  = g_pts[s_own * CAP + u];
    const float px = p.x, py = p.y, pz = p.z;
    const float p2 = -2.0f * p.w;
    const int cx = cell_coord(px), cy = cell_coord(py), cz = cell_coord(pz);

    const int*    st  = g_start + s * NCELL;
    const int*    cu  = g_cur   + s * NCELL;
    const float4* pts = g_pts   + s * CAP;

    float m = -CUDART_INF_F;

    // rings 0..1: 9 rows; lanes 0..8 fetch row ranges in parallel
    {
        const int x0 = max(cx - 1, 0), x1 = min(cx + 1, G - 1);
        int beg = 0, end = 0;
        if (lane < 9) {
            const int dz = lane / 3 - 1, dy = lane % 3 - 1;
            const int zz = min(max(cz + dz, 0), G - 1);
            const int yy = min(max(cy + dy, 0), G - 1);
            const int rb = (zz * G + yy) * G;
            beg = st[rb + x0];
            end = cu[rb + x1];
        }
        #pragma unroll
        for (int k = 0; k < 9; k++) {
            const int b = __shfl_sync(0xffffffffu, beg, k);
            const int e = __shfl_sync(0xffffffffu, end, k);
            for (int v = b + lane; v < e; v += 32) {
                const float4 q = pts[v];
                m = fmaxf(m, fmaf(px, q.x, fmaf(py, q.y, fmaf(pz, q.z, q.w))));
            }
        }
    }
    // warp max
    #pragma unroll
    for (int o = 16; o; o >>= 1)
        m = fmaxf(m, __shfl_xor_sync(0xffffffffu, m, o));
    float bd2 = fmaf(-2.0f, m, p2);

    // shells r >= 2: (2r+1)^2 rows distributed across lanes
    for (int r = 2; r < G; r++) {
        const float bound = (float)(r - 1) * H;
        if (bd2 <= bound * bound) break;     // warp-uniform

        const int W  = 2 * r + 1;
        const int NP = W * W;
        float ml = m;
        for (int idx = lane; idx < NP; idx += 32) {
            const int dz = idx / W - r;
            const int dy = idx - (dz + r) * W - r;
            const int zz = cz + dz;
            const int yy = cy + dy;
            if (zz < 0 || zz >= G || yy < 0 || yy >= G) continue;
            const int rb = (zz * G + yy) * G;
            if (dz == -r || dz == r || dy == -r || dy == r) {
                const int x0 = max(cx - r, 0), x1 = min(cx + r, G - 1);
                const int beg = st[rb + x0], end = cu[rb + x1];
                for (int v = beg; v < end; v++) {
                    const float4 q = pts[v];
                    ml = fmaxf(ml, fmaf(px, q.x, fmaf(py, q.y, fmaf(pz, q.z, q.w))));
                }
            } else {
                const int xl = cx - r;
                if (xl >= 0) {
                    const int beg = st[rb + xl], end = cu[rb + xl];
                    for (int v = beg; v < end; v++) {
                        const float4 q = pts[v];
                        ml = fmaxf(ml, fmaf(px, q.x, fmaf(py, q.y, fmaf(pz, q.z, q.w))));
                    }
                }
                const int xr = cx + r;
                if (xr < G) {
                    const int beg = st[rb + xr], end = cu[rb + xr];
                    for (int v = beg; v < end; v++) {
                        const float4 q = pts[v];
                        ml = fmaxf(ml, fmaf(px, q.x, fmaf(py, q.y, fmaf(pz, q.z, q.w))));
                    }
                }
            }
        }
        #pragma unroll
        for (int o = 16; o; o >>= 1)
            ml = fmaxf(ml, __shfl_xor_sync(0xffffffffu, ml, o));
        m = ml;
        bd2 = fmaf(-2.0f, m, p2);
    }

    // block reduction of 32 per-warp values -> g_blocksum[block]
    __shared__ float ws[32];
    if (lane == 0) ws[threadIdx.x >> 5] = bd2 * scale;
    __syncthreads();
    if (threadIdx.x < 32) {
        float v = ws[threadIdx.x];
        #pragma unroll
        for (int o = 16; o; o >>= 1)
            v += __shfl_xor_sync(0xffffffffu, v, o);
        if (threadIdx.x == 0) g_blocksum[blockIdx.x] = v;
    }
}

__global__ __launch_bounds__(1024) void k_final(float* __restrict__ out) {
    const int tid = threadIdx.x;
    float v = 0.0f;
    #pragma unroll
    for (int k = 0; k < QBLOCKS / 1024; k++)
        v += g_blocksum[tid + k * 1024];
    #pragma unroll
    for (int o = 16; o; o >>= 1)
        v += __shfl_xor_sync(0xffffffffu, v, o);
    __shared__ float ws[32];
    if ((tid & 31) == 0) ws[tid >> 5] = v;
    __syncthreads();
    if (tid < 32) {
        float x = ws[tid];
        #pragma unroll
        for (int o = 16; o; o >>= 1)
            x += __shfl_xor_sync(0xffffffffu, x, o);
        if (tid == 0) out[0] = x;
    }
}

extern "C" void kernel_launch(void* const* d_in, const int* in_sizes, int n_in,
                              void* d_out, int out_size) {
    const float* pf = (const float*)d_in[0];
    const float* gf = (const float*)d_in[1];
    const float* pn = (const float*)d_in[2];
    const float* gn = (const float*)d_in[3];
    float* out = (float*)d_out;

    k_zero<<<(NSTRUCT * NCELL + 1023) / 1024, 1024>>>();
    k_count<<<NQ_TOTAL / 256, 256>>>(pf, gf, pn, gn);
    k_scan<<<NSTRUCT, 1024>>>();
    k_scatter<<<NQ_TOTAL / 256, 256>>>(pf, gf, pn, gn);
    k_query<<<QBLOCKS, 1024>>>();
    k_final<<<1, 1024>>>(out);
}

// round 7
// speedup vs baseline: 1.4016x; 1.1626x over previous
#include <cuda_runtime.h>
#include <math_constants.h>

// ChamferLoss via exact grid NN. One warp per query, 4 warps per block
// (small scheduling quantum -> Gaussian-tail queries don't stall waves),
// with an exact cube-face termination bound.
// d2min(p -> Q) = |p|^2 - 2 * max_j ( p.q_j - 0.5|q_j|^2 )
//
// 16 structures: s in [0,8) nonfiltered (0-3 pn, 4-7 gn, 8192 pts),
//                s in [8,16) filtered (8-11 pf, 12-15 gf, 4096 pts).
// Structure s queries partner s^4.
//
// Exactness: after scanning the full (clamped) index cube of radius r around
// the query's cell, any unscanned cell differs by >= r+1 in some axis index,
// so any unscanned point lies beyond the scanned cube's face along that axis:
// dist >= min_a min(p_a - lo_a, hi_a - p_a) (inf on clamped sides). We stop
// when bd2 <= (0.9999*bound)^2. Duplicate clamped rows rescan cells; max is
// idempotent so it's harmless.

#define G     32
#define NCELL (G * G * G)
#define H     0.32f
#define INVH  3.125f
#define RANGE 5.12f
#define NSTRUCT 16
#define CAP   8192

#define NQ_TOTAL 98304
#define QWARPS   4                       // queries (warps) per block
#define QBLK     (QWARPS * 32)
#define QBLOCKS  (NQ_TOTAL / QWARPS)     // 24576 blocks

__device__ int    g_cnt  [NSTRUCT * NCELL];
__device__ int    g_start[NSTRUCT * NCELL];
__device__ int    g_cur  [NSTRUCT * NCELL];
__device__ float4 g_pts  [NSTRUCT * CAP];     // cell-sorted (x,y,z,-0.5|q|^2)
__device__ float  g_blocksum[QBLOCKS];

__device__ __forceinline__ int cell_coord(float x) {
    int c = (int)floorf((x + RANGE) * INVH);
    return min(max(c, 0), G - 1);
}

__device__ __forceinline__ const float* map_point(
    int t, const float* pf, const float* gf, const float* pn, const float* gn,
    int* idx, int* s)
{
    if (t < 65536) {
        const int grp = t >> 13;
        *idx = t & 8191;
        *s   = grp;
        return ((grp < 4) ? pn : gn) + (size_t)(grp & 3) * 8192 * 3;
    } else {
        const int tf  = t - 65536;
        const int grp = tf >> 12;
        *idx = tf & 4095;
        *s   = 8 + grp;
        return ((grp < 4) ? pf : gf) + (size_t)(grp & 3) * 4096 * 3;
    }
}

__global__ void k_zero() {
    const int i = blockIdx.x * 1024 + threadIdx.x;
    if (i < NSTRUCT * NCELL) g_cnt[i] = 0;
}

__global__ __launch_bounds__(256) void k_count(
    const float* __restrict__ pf, const float* __restrict__ gf,
    const float* __restrict__ pn, const float* __restrict__ gn)
{
    const int t = blockIdx.x * 256 + threadIdx.x;
    int i, s;
    const float* P = map_point(t, pf, gf, pn, gn, &i, &s);
    const float x = P[3 * i], y = P[3 * i + 1], z = P[3 * i + 2];
    const int cell = (cell_coord(z) * G + cell_coord(y)) * G + cell_coord(x);
    atomicAdd(&g_cnt[s * NCELL + cell], 1);
}

__global__ __launch_bounds__(1024) void k_scan() {
    const int s   = blockIdx.x;
    const int tid = threadIdx.x;
    const int CPT = NCELL / 1024;
    const int base = s * NCELL + tid * CPT;

    int sum = 0;
    #pragma unroll
    for (int k = 0; k < CPT; k++) sum += g_cnt[base + k];

    __shared__ int sh[1024];
    sh[tid] = sum;
    __syncthreads();
    #pragma unroll
    for (int off = 1; off < 1024; off <<= 1) {
        int v = (tid >= off) ? sh[tid - off] : 0;
        __syncthreads();
        sh[tid] += v;
        __syncthreads();
    }
    int run = (tid == 0) ? 0 : sh[tid - 1];

    #pragma unroll
    for (int k = 0; k < CPT; k++) {
        const int c = g_cnt[base + k];
        g_start[base + k] = run;
        g_cur[base + k]   = run;
        run += c;
    }
}

__global__ __launch_bounds__(256) void k_scatter(
    const float* __restrict__ pf, const float* __restrict__ gf,
    const float* __restrict__ pn, const float* __restrict__ gn)
{
    const int t = blockIdx.x * 256 + threadIdx.x;
    int i, s;
    const float* P = map_point(t, pf, gf, pn, gn, &i, &s);
    const float x = P[3 * i], y = P[3 * i + 1], z = P[3 * i + 2];
    const int cell = (cell_coord(z) * G + cell_coord(y)) * G + cell_coord(x);
    const int slot = atomicAdd(&g_cur[s * NCELL + cell], 1);
    const float nh = -0.5f * fmaf(x, x, fmaf(y, y, z * z));
    g_pts[s * CAP + slot] = make_float4(x, y, z, nh);
}

// exact lower bound on distance to anything OUTSIDE the scanned index cube
// [c-r, c+r]^3 (clamped sides are exhaustively scanned -> infinite margin)
__device__ __forceinline__ float cube_bound(
    float px, float py, float pz, int cx, int cy, int cz, int r)
{
    float b = CUDART_INF_F;
    if (cx - r > 0)     b = fminf(b, px - (-RANGE + (float)(cx - r) * H));
    if (cx + r < G - 1) b = fminf(b, (-RANGE + (float)(cx + r + 1) * H) - px);
    if (cy - r > 0)     b = fminf(b, py - (-RANGE + (float)(cy - r) * H));
    if (cy + r < G - 1) b = fminf(b, (-RANGE + (float)(cy + r + 1) * H) - py);
    if (cz - r > 0)     b = fminf(b, pz - (-RANGE + (float)(cz - r) * H));
    if (cz + r < G - 1) b = fminf(b, (-RANGE + (float)(cz + r + 1) * H) - pz);
    return fmaxf(b * 0.9999f, 0.0f);   // float-safety margin
}

// ---- one warp per query, QWARPS warps per block ----
__global__ __launch_bounds__(QBLK) void k_query()
{
    const int wq   = blockIdx.x * QWARPS + (threadIdx.x >> 5);
    const int lane = threadIdx.x & 31;

    int s_own, u;
    float scale;
    if (wq < 65536) {
        s_own = wq >> 13;
        u     = wq & 8191;
        scale = 0.3f / (4.0f * 8192.0f);
    } else {
        const int tf = wq - 65536;
        s_own = 8 + (tf >> 12);
        u     = tf & 4095;
        scale = 0.7f / (4.0f * 4096.0f);
    }
    const int s = s_own ^ 4;

    const float4 p  = g_pts[s_own * CAP + u];
    const float px = p.x, py = p.y, pz = p.z;
    const float p2 = -2.0f * p.w;
    const int cx = cell_coord(px), cy = cell_coord(py), cz = cell_coord(pz);

    const int*    st  = g_start + s * NCELL;
    const int*    cu  = g_cur   + s * NCELL;
    const float4* pts = g_pts   + s * CAP;

    float m = -CUDART_INF_F;

    // cube r=1 (3x3x3): 9 rows; lanes 0..8 fetch row ranges in parallel
    {
        const int x0 = max(cx - 1, 0), x1 = min(cx + 1, G - 1);
        int beg = 0, end = 0;
        if (lane < 9) {
            const int dz = lane / 3 - 1, dy = lane % 3 - 1;
            const int zz = min(max(cz + dz, 0), G - 1);
            const int yy = min(max(cy + dy, 0), G - 1);
            const int rb = (zz * G + yy) * G;
            beg = st[rb + x0];
            end = cu[rb + x1];
        }
        #pragma unroll
        for (int k = 0; k < 9; k++) {
            const int b = __shfl_sync(0xffffffffu, beg, k);
            const int e = __shfl_sync(0xffffffffu, end, k);
            for (int v = b + lane; v < e; v += 32) {
                const float4 q = pts[v];
                m = fmaxf(m, fmaf(px, q.x, fmaf(py, q.y, fmaf(pz, q.z, q.w))));
            }
        }
    }
    #pragma unroll
    for (int o = 16; o; o >>= 1)
        m = fmaxf(m, __shfl_xor_sync(0xffffffffu, m, o));
    float bd2 = fmaf(-2.0f, m, p2);

    // expand shells while the scanned cube can't certify the minimum
    for (int r = 1; r < G - 1; r++) {
        const float bound = cube_bound(px, py, pz, cx, cy, cz, r);
        if (bd2 <= bound * bound) break;          // warp-uniform

        const int rs = r + 1;                      // shell to scan now
        const int W  = 2 * rs + 1;
        const int NP = W * W;
        float ml = m;
        for (int idx = lane; idx < NP; idx += 32) {
            const int dz = idx / W - rs;
            const int dy = idx - (dz + rs) * W - rs;
            const int zz = cz + dz;
            const int yy = cy + dy;
            if (zz < 0 || zz >= G || yy < 0 || yy >= G) continue;
            const int rb = (zz * G + yy) * G;
            if (dz == -rs || dz == rs || dy == -rs || dy == rs) {
                const int x0 = max(cx - rs, 0), x1 = min(cx + rs, G - 1);
                const int beg = st[rb + x0], end = cu[rb + x1];
                for (int v = beg; v < end; v++) {
                    const float4 q = pts[v];
                    ml = fmaxf(ml, fmaf(px, q.x, fmaf(py, q.y, fmaf(pz, q.z, q.w))));
                }
            } else {
                const int xl = cx - rs;
                if (xl >= 0) {
                    const int beg = st[rb + xl], end = cu[rb + xl];
                    for (int v = beg; v < end; v++) {
                        const float4 q = pts[v];
                        ml = fmaxf(ml, fmaf(px, q.x, fmaf(py, q.y, fmaf(pz, q.z, q.w))));
                    }
                }
                const int xr = cx + rs;
                if (xr < G) {
                    const int beg = st[rb + xr], end = cu[rb + xr];
                    for (int v = beg; v < end; v++) {
                        const float4 q = pts[v];
                        ml = fmaxf(ml, fmaf(px, q.x, fmaf(py, q.y, fmaf(pz, q.z, q.w))));
                    }
                }
            }
        }
        #pragma unroll
        for (int o = 16; o; o >>= 1)
            ml = fmaxf(ml, __shfl_xor_sync(0xffffffffu, ml, o));
        m = ml;
        bd2 = fmaf(-2.0f, m, p2);
    }

    // block reduction of QWARPS per-warp values
    __shared__ float ws[QWARPS];
    if (lane == 0) ws[threadIdx.x >> 5] = bd2 * scale;
    __syncthreads();
    if (threadIdx.x == 0) {
        float v = 0.0f;
        #pragma unroll
        for (int w = 0; w < QWARPS; w++) v += ws[w];
        g_blocksum[blockIdx.x] = v;
    }
}

__global__ __launch_bounds__(1024) void k_final(float* __restrict__ out) {
    const int tid = threadIdx.x;
    float v = 0.0f;
    #pragma unroll
    for (int k = 0; k < QBLOCKS / 1024; k++)
        v += g_blocksum[tid + k * 1024];
    #pragma unroll
    for (int o = 16; o; o >>= 1)
        v += __shfl_xor_sync(0xffffffffu, v, o);
    __shared__ float ws[32];
    if ((tid & 31) == 0) ws[tid >> 5] = v;
    __syncthreads();
    if (tid < 32) {
        float x = ws[tid];
        #pragma unroll
        for (int o = 16; o; o >>= 1)
            x += __shfl_xor_sync(0xffffffffu, x, o);
        if (tid == 0) out[0] = x;
    }
}

extern "C" void kernel_launch(void* const* d_in, const int* in_sizes, int n_in,
                              void* d_out, int out_size) {
    const float* pf = (const float*)d_in[0];
    const float* gf = (const float*)d_in[1];
    const float* pn = (const float*)d_in[2];
    const float* gn = (const float*)d_in[3];
    float* out = (float*)d_out;

    k_zero<<<(NSTRUCT * NCELL + 1023) / 1024, 1024>>>();
    k_count<<<NQ_TOTAL / 256, 256>>>(pf, gf, pn, gn);
    k_scan<<<NSTRUCT, 1024>>>();
    k_scatter<<<NQ_TOTAL / 256, 256>>>(pf, gf, pn, gn);
    k_query<<<QBLOCKS, QBLK>>>();
    k_final<<<1, 1024>>>(out);
}

// round 8
// speedup vs baseline: 1.5209x; 1.0851x over previous
#include <cuda_runtime.h>
#include <math_constants.h>

// ChamferLoss via exact grid NN. One warp per query; the 3x3x3 neighborhood
// scan is FLATTENED into a single union index space so all candidate loads
// are independent (MLP across rows) instead of 9 serial row latencies.
// d2min(p -> Q) = |p|^2 - 2 * max_j ( p.q_j - 0.5|q_j|^2 )
//
// 16 structures: s in [0,8) nonfiltered (0-3 pn, 4-7 gn, 8192 pts),
//                s in [8,16) filtered (8-11 pf, 12-15 gf, 4096 pts).
// Structure s queries partner s^4.
//
// Exactness: after scanning the full (clamped) index cube of radius r, any
// unscanned point lies beyond a scanned face: dist >= min over unclamped
// axes of the margin from p to the cube face. Stop when bd2 <= (0.9999*b)^2.
// Clamped duplicate rows rescan cells; max is idempotent so it's harmless.

#define G     32
#define NCELL (G * G * G)
#define H     0.32f
#define INVH  3.125f
#define RANGE 5.12f
#define NSTRUCT 16
#define CAP   8192

#define NQ_TOTAL 98304
#define QWARPS   4
#define QBLK     (QWARPS * 32)
#define QBLOCKS  (NQ_TOTAL / QWARPS)

__device__ int    g_cnt  [NSTRUCT * NCELL];
__device__ int    g_start[NSTRUCT * NCELL];
__device__ int    g_cur  [NSTRUCT * NCELL];
__device__ float4 g_pts  [NSTRUCT * CAP];
__device__ float  g_blocksum[QBLOCKS];

__device__ __forceinline__ int cell_coord(float x) {
    int c = (int)floorf((x + RANGE) * INVH);
    return min(max(c, 0), G - 1);
}

__device__ __forceinline__ const float* map_point(
    int t, const float* pf, const float* gf, const float* pn, const float* gn,
    int* idx, int* s)
{
    if (t < 65536) {
        const int grp = t >> 13;
        *idx = t & 8191;
        *s   = grp;
        return ((grp < 4) ? pn : gn) + (size_t)(grp & 3) * 8192 * 3;
    } else {
        const int tf  = t - 65536;
        const int grp = tf >> 12;
        *idx = tf & 4095;
        *s   = 8 + grp;
        return ((grp < 4) ? pf : gf) + (size_t)(grp & 3) * 4096 * 3;
    }
}

__global__ void k_zero() {
    const int i = blockIdx.x * 1024 + threadIdx.x;
    if (i < NSTRUCT * NCELL) g_cnt[i] = 0;
}

__global__ __launch_bounds__(256) void k_count(
    const float* __restrict__ pf, const float* __restrict__ gf,
    const float* __restrict__ pn, const float* __restrict__ gn)
{
    const int t = blockIdx.x * 256 + threadIdx.x;
    int i, s;
    const float* P = map_point(t, pf, gf, pn, gn, &i, &s);
    const float x = P[3 * i], y = P[3 * i + 1], z = P[3 * i + 2];
    const int cell = (cell_coord(z) * G + cell_coord(y)) * G + cell_coord(x);
    atomicAdd(&g_cnt[s * NCELL + cell], 1);
}

__global__ __launch_bounds__(1024) void k_scan() {
    const int s   = blockIdx.x;
    const int tid = threadIdx.x;
    const int CPT = NCELL / 1024;
    const int base = s * NCELL + tid * CPT;

    int sum = 0;
    #pragma unroll
    for (int k = 0; k < CPT; k++) sum += g_cnt[base + k];

    __shared__ int sh[1024];
    sh[tid] = sum;
    __syncthreads();
    #pragma unroll
    for (int off = 1; off < 1024; off <<= 1) {
        int v = (tid >= off) ? sh[tid - off] : 0;
        __syncthreads();
        sh[tid] += v;
        __syncthreads();
    }
    int run = (tid == 0) ? 0 : sh[tid - 1];

    #pragma unroll
    for (int k = 0; k < CPT; k++) {
        const int c = g_cnt[base + k];
        g_start[base + k] = run;
        g_cur[base + k]   = run;
        run += c;
    }
}

__global__ __launch_bounds__(256) void k_scatter(
    const float* __restrict__ pf, const float* __restrict__ gf,
    const float* __restrict__ pn, const float* __restrict__ gn)
{
    const int t = blockIdx.x * 256 + threadIdx.x;
    int i, s;
    const float* P = map_point(t, pf, gf, pn, gn, &i, &s);
    const float x = P[3 * i], y = P[3 * i + 1], z = P[3 * i + 2];
    const int cell = (cell_coord(z) * G + cell_coord(y)) * G + cell_coord(x);
    const int slot = atomicAdd(&g_cur[s * NCELL + cell], 1);
    const float nh = -0.5f * fmaf(x, x, fmaf(y, y, z * z));
    g_pts[s * CAP + slot] = make_float4(x, y, z, nh);
}

__device__ __forceinline__ float cube_bound(
    float px, float py, float pz, int cx, int cy, int cz, int r)
{
    float b = CUDART_INF_F;
    if (cx - r > 0)     b = fminf(b, px - (-RANGE + (float)(cx - r) * H));
    if (cx + r < G - 1) b = fminf(b, (-RANGE + (float)(cx + r + 1) * H) - px);
    if (cy - r > 0)     b = fminf(b, py - (-RANGE + (float)(cy - r) * H));
    if (cy + r < G - 1) b = fminf(b, (-RANGE + (float)(cy + r + 1) * H) - py);
    if (cz - r > 0)     b = fminf(b, pz - (-RANGE + (float)(cz - r) * H));
    if (cz + r < G - 1) b = fminf(b, (-RANGE + (float)(cz + r + 1) * H) - pz);
    return fmaxf(b * 0.9999f, 0.0f);
}

__global__ __launch_bounds__(QBLK) void k_query()
{
    const int wq   = blockIdx.x * QWARPS + (threadIdx.x >> 5);
    const int lane = threadIdx.x & 31;

    int s_own, u;
    float scale;
    if (wq < 65536) {
        s_own = wq >> 13;
        u     = wq & 8191;
        scale = 0.3f / (4.0f * 8192.0f);
    } else {
        const int tf = wq - 65536;
        s_own = 8 + (tf >> 12);
        u     = tf & 4095;
        scale = 0.7f / (4.0f * 4096.0f);
    }
    const int s = s_own ^ 4;

    const float4 p  = g_pts[s_own * CAP + u];
    const float px = p.x, py = p.y, pz = p.z;
    const float p2 = -2.0f * p.w;
    const int cx = cell_coord(px), cy = cell_coord(py), cz = cell_coord(pz);

    const int*    st  = g_start + s * NCELL;
    const int*    cu  = g_cur   + s * NCELL;
    const float4* pts = g_pts   + s * CAP;

    float m = -CUDART_INF_F;

    // ---- ring<=1 cube: 9 rows fetched in parallel, scanned as ONE union ----
    {
        const int x0 = max(cx - 1, 0), x1 = min(cx + 1, G - 1);
        int beg = 0, end = 0;
        if (lane < 9) {
            const int dz = lane / 3 - 1, dy = lane % 3 - 1;
            const int zz = min(max(cz + dz, 0), G - 1);
            const int yy = min(max(cy + dy, 0), G - 1);
            const int rb = (zz * G + yy) * G;
            beg = st[rb + x0];
            end = cu[rb + x1];
        }

        // broadcast all 9 ranges; build union offsets + per-row deltas
        int off1, off2, off3, off4, off5, off6, off7, off8, T;
        int dl0, dl1, dl2, dl3, dl4, dl5, dl6, dl7, dl8;
        {
            int o = 0;
            int b, e;
            b = __shfl_sync(0xffffffffu, beg, 0); e = __shfl_sync(0xffffffffu, end, 0);
            dl0 = b - o; o += e - b; off1 = o;
            b = __shfl_sync(0xffffffffu, beg, 1); e = __shfl_sync(0xffffffffu, end, 1);
            dl1 = b - o; o += e - b; off2 = o;
            b = __shfl_sync(0xffffffffu, beg, 2); e = __shfl_sync(0xffffffffu, end, 2);
            dl2 = b - o; o += e - b; off3 = o;
            b = __shfl_sync(0xffffffffu, beg, 3); e = __shfl_sync(0xffffffffu, end, 3);
            dl3 = b - o; o += e - b; off4 = o;
            b = __shfl_sync(0xffffffffu, beg, 4); e = __shfl_sync(0xffffffffu, end, 4);
            dl4 = b - o; o += e - b; off5 = o;
            b = __shfl_sync(0xffffffffu, beg, 5); e = __shfl_sync(0xffffffffu, end, 5);
            dl5 = b - o; o += e - b; off6 = o;
            b = __shfl_sync(0xffffffffu, beg, 6); e = __shfl_sync(0xffffffffu, end, 6);
            dl6 = b - o; o += e - b; off7 = o;
            b = __shfl_sync(0xffffffffu, beg, 7); e = __shfl_sync(0xffffffffu, end, 7);
            dl7 = b - o; o += e - b; off8 = o;
            b = __shfl_sync(0xffffffffu, beg, 8); e = __shfl_sync(0xffffffffu, end, 8);
            dl8 = b - o; o += e - b; T = o;
        }

        // one flattened loop: every load independent -> full MLP
        for (int idx = lane; idx < T; idx += 32) {
            int d = dl0;
            d = (idx >= off1) ? dl1 : d;
            d = (idx >= off2) ? dl2 : d;
            d = (idx >= off3) ? dl3 : d;
            d = (idx >= off4) ? dl4 : d;
            d = (idx >= off5) ? dl5 : d;
            d = (idx >= off6) ? dl6 : d;
            d = (idx >= off7) ? dl7 : d;
            d = (idx >= off8) ? dl8 : d;
            const float4 q = pts[idx + d];
            m = fmaxf(m, fmaf(px, q.x, fmaf(py, q.y, fmaf(pz, q.z, q.w))));
        }
    }
    #pragma unroll
    for (int o = 16; o; o >>= 1)
        m = fmaxf(m, __shfl_xor_sync(0xffffffffu, m, o));
    float bd2 = fmaf(-2.0f, m, p2);

    // ---- shell expansion (rare): lane-parallel rows ----
    for (int r = 1; r < G - 1; r++) {
        const float bound = cube_bound(px, py, pz, cx, cy, cz, r);
        if (bd2 <= bound * bound) break;

        const int rs = r + 1;
        const int W  = 2 * rs + 1;
        const int NP = W * W;
        float ml = m;
        for (int idx = lane; idx < NP; idx += 32) {
            const int dz = idx / W - rs;
            const int dy = idx - (dz + rs) * W - rs;
            const int zz = cz + dz;
            const int yy = cy + dy;
            if (zz < 0 || zz >= G || yy < 0 || yy >= G) continue;
            const int rb = (zz * G + yy) * G;
            if (dz == -rs || dz == rs || dy == -rs || dy == rs) {
                const int x0 = max(cx - rs, 0), x1 = min(cx + rs, G - 1);
                const int beg = st[rb + x0], end = cu[rb + x1];
                for (int v = beg; v < end; v++) {
                    const float4 q = pts[v];
                    ml = fmaxf(ml, fmaf(px, q.x, fmaf(py, q.y, fmaf(pz, q.z, q.w))));
                }
            } else {
                const int xl = cx - rs;
                if (xl >= 0) {
                    const int beg = st[rb + xl], end = cu[rb + xl];
                    for (int v = beg; v < end; v++) {
                        const float4 q = pts[v];
                        ml = fmaxf(ml, fmaf(px, q.x, fmaf(py, q.y, fmaf(pz, q.z, q.w))));
                    }
                }
                const int xr = cx + rs;
                if (xr < G) {
                    const int beg = st[rb + xr], end = cu[rb + xr];
                    for (int v = beg; v < end; v++) {
                        const float4 q = pts[v];
                        ml = fmaxf(ml, fmaf(px, q.x, fmaf(py, q.y, fmaf(pz, q.z, q.w))));
                    }
                }
            }
        }
        #pragma unroll
        for (int o = 16; o; o >>= 1)
            ml = fmaxf(ml, __shfl_xor_sync(0xffffffffu, ml, o));
        m = ml;
        bd2 = fmaf(-2.0f, m, p2);
    }

    __shared__ float ws[QWARPS];
    if (lane == 0) ws[threadIdx.x >> 5] = bd2 * scale;
    __syncthreads();
    if (threadIdx.x == 0) {
        float v = 0.0f;
        #pragma unroll
        for (int w = 0; w < QWARPS; w++) v += ws[w];
        g_blocksum[blockIdx.x] = v;
    }
}

__global__ __launch_bounds__(1024) void k_final(float* __restrict__ out) {
    const int tid = threadIdx.x;
    float v = 0.0f;
    #pragma unroll
    for (int k = 0; k < QBLOCKS / 1024; k++)
        v += g_blocksum[tid + k * 1024];
    #pragma unroll
    for (int o = 16; o; o >>= 1)
        v += __shfl_xor_sync(0xffffffffu, v, o);
    __shared__ float ws[32];
    if ((tid & 31) == 0) ws[tid >> 5] = v;
    __syncthreads();
    if (tid < 32) {
        float x = ws[tid];
        #pragma unroll
        for (int o = 16; o; o >>= 1)
            x += __shfl_xor_sync(0xffffffffu, x, o);
        if (tid == 0) out[0] = x;
    }
}

extern "C" void kernel_launch(void* const* d_in, const int* in_sizes, int n_in,
                              void* d_out, int out_size) {
    const float* pf = (const float*)d_in[0];
    const float* gf = (const float*)d_in[1];
    const float* pn = (const float*)d_in[2];
    const float* gn = (const float*)d_in[3];
    float* out = (float*)d_out;

    k_zero<<<(NSTRUCT * NCELL + 1023) / 1024, 1024>>>();
    k_count<<<NQ_TOTAL / 256, 256>>>(pf, gf, pn, gn);
    k_scan<<<NSTRUCT, 1024>>>();
    k_scatter<<<NQ_TOTAL / 256, 256>>>(pf, gf, pn, gn);
    k_query<<<QBLOCKS, QBLK>>>();
    k_final<<<1, 1024>>>(out);
}